// round 2
// baseline (speedup 1.0000x reference)
#include <cuda_runtime.h>
#include <cstdint>

#define TT   1024
#define BB   64
#define DIN  400
#define HH   128
#define G4   512
#define HD1  256
#define HD2  64
#define NROW (TT*BB)

// ---------------- scratch (device globals; no runtime allocation) ----------------
__device__ float g_G  [(size_t)2*NROW*G4];   // gate preactivations, both dirs (reused per layer)
__device__ float g_X1 [(size_t)NROW*HD1];    // layer0 output [t][b][256]
__device__ float g_X2 [(size_t)NROW*HD1];    // layer1 output [t][b][256]
__device__ float g_HL [(size_t)NROW*2];      // precomputed h-part of logits
__device__ float g_Wp [HD2*HD1];             // BN1-folded linear weight
__device__ float g_bp [HD2];                 // BN1-folded linear bias
__device__ float g_Wh2[2*HD2];               // BN2-folded output weight (h part)
__device__ float g_hb [2];                   // BN2-folded output bias

// ---------------- prep: fold BN1/BN2 into linear / output weights ----------------
__global__ void k_prep(const float* bn1g, const float* bn1b, const float* bn1m, const float* bn1v,
                       const float* linw, const float* linb,
                       const float* bn2g, const float* bn2b, const float* bn2m, const float* bn2v,
                       const float* outw, const float* outb) {
    __shared__ float s1[HD1], t1[HD1], s2[HD2], t2[HD2];
    int tid = threadIdx.x;
    if (tid < HD1) { float s = bn1g[tid]*rsqrtf(bn1v[tid]+1e-5f); s1[tid]=s; t1[tid]=bn1b[tid]-bn1m[tid]*s; }
    if (tid < HD2) { float s = bn2g[tid]*rsqrtf(bn2v[tid]+1e-5f); s2[tid]=s; t2[tid]=bn2b[tid]-bn2m[tid]*s; }
    __syncthreads();
    for (int i = tid; i < HD2*HD1; i += blockDim.x) g_Wp[i] = linw[i]*s1[i & (HD1-1)];
    if (tid < HD2) {
        float a = linb[tid];
        for (int j = 0; j < HD1; j++) a += t1[j]*linw[tid*HD1+j];
        g_bp[tid] = a;
    }
    if (tid < 2*HD2) { int k = tid>>6, c = tid&63; g_Wh2[tid] = outw[k*68+4+c]*s2[c]; }
    if (tid < 2) {
        float a = outb[tid];
        for (int c = 0; c < HD2; c++) a += t2[c]*outw[tid*68+4+c];
        g_hb[tid] = a;
    }
}

// ---------------- input-projection GEMM: G[d][t*B+b][j] = A[row]·W_d[j] + bias ----------------
__global__ void __launch_bounds__(256) k_gemm(
    const float* __restrict__ x,
    const float* __restrict__ Wf, const float* __restrict__ bif, const float* __restrict__ bhf,
    const float* __restrict__ Wr, const float* __restrict__ bir, const float* __restrict__ bhr,
    int Kdim, int layer)
{
    __shared__ float as[16][64];
    __shared__ float bs[16][64];
    int tid  = threadIdx.x;
    int row0 = blockIdx.x*64, col0 = blockIdx.y*64;
    int dir  = blockIdx.z;
    const float* W  = dir ? Wr  : Wf;
    const float* bi = dir ? bir : bif;
    const float* bh = dir ? bhr : bhf;

    int lr = tid >> 2;            // 0..63
    int kq = (tid & 3) * 4;       // 0,4,8,12
    const float* arow;
    {
        int r = row0 + lr;
        if (layer == 0) { int t = r >> 6, b = r & 63; arow = x + ((size_t)b*TT + t)*DIN; }
        else            { arow = g_X1 + (size_t)r*HD1; }
    }
    const float* wrow = W + (size_t)(col0 + lr)*Kdim;

    int rowgrp = tid >> 4;        // 0..15 -> rows rowgrp*4..+3
    int colgrp = tid & 15;        // 0..15 -> cols colgrp*4..+3
    float acc[4][4];
#pragma unroll
    for (int i = 0; i < 4; i++)
#pragma unroll
        for (int j = 0; j < 4; j++) acc[i][j] = 0.f;

    int nkt = Kdim >> 4;
    for (int kt = 0; kt < nkt; ++kt) {
        int k0 = kt*16;
        float4 av = *(const float4*)(arow + k0 + kq);
        float4 bv = *(const float4*)(wrow + k0 + kq);
        __syncthreads();
        as[kq+0][lr]=av.x; as[kq+1][lr]=av.y; as[kq+2][lr]=av.z; as[kq+3][lr]=av.w;
        bs[kq+0][lr]=bv.x; bs[kq+1][lr]=bv.y; bs[kq+2][lr]=bv.z; bs[kq+3][lr]=bv.w;
        __syncthreads();
#pragma unroll
        for (int kk = 0; kk < 16; ++kk) {
            float4 a4 = *(const float4*)&as[kk][rowgrp*4];
            float4 b4 = *(const float4*)&bs[kk][colgrp*4];
            acc[0][0]+=a4.x*b4.x; acc[0][1]+=a4.x*b4.y; acc[0][2]+=a4.x*b4.z; acc[0][3]+=a4.x*b4.w;
            acc[1][0]+=a4.y*b4.x; acc[1][1]+=a4.y*b4.y; acc[1][2]+=a4.y*b4.z; acc[1][3]+=a4.y*b4.w;
            acc[2][0]+=a4.z*b4.x; acc[2][1]+=a4.z*b4.y; acc[2][2]+=a4.z*b4.z; acc[2][3]+=a4.z*b4.w;
            acc[3][0]+=a4.w*b4.x; acc[3][1]+=a4.w*b4.y; acc[3][2]+=a4.w*b4.z; acc[3][3]+=a4.w*b4.w;
        }
    }
    int jc = col0 + colgrp*4;
    float4 bias;
    bias.x = bi[jc+0]+bh[jc+0]; bias.y = bi[jc+1]+bh[jc+1];
    bias.z = bi[jc+2]+bh[jc+2]; bias.w = bi[jc+3]+bh[jc+3];
    float* Cb = g_G + (size_t)dir*NROW*G4;
#pragma unroll
    for (int i = 0; i < 4; i++) {
        int r = row0 + rowgrp*4 + i;
        float4 v;
        v.x = acc[i][0]+bias.x; v.y = acc[i][1]+bias.y;
        v.z = acc[i][2]+bias.z; v.w = acc[i][3]+bias.w;
        *(float4*)(Cb + (size_t)r*G4 + jc) = v;
    }
}

// ---------------- recurrent scan: cluster of 2 CTAs, n-split, batch-chunked ----------------
// grid: (64, 2) = (32 chunks * 2 ctarank, 2 dirs); 512 threads; dynamic smem.
#define PSTRIDE 20
#define SCAN_SMEM_FLOATS (32768 + 512*PSTRIDE + 512 + 512)

__device__ __forceinline__ float sigf(float x) { return 1.f/(1.f + __expf(-x)); }

__global__ __launch_bounds__(512, 1) __cluster_dims__(2, 1, 1)
void k_scan(const float* __restrict__ WhhF, const float* __restrict__ WhhB, int layer)
{
    extern __shared__ float sm[];
    float* wt   = sm;                       // [128][256] weights, k-major
    float* part = sm + 32768;               // [512][PSTRIDE] partials
    float* gbuf = part + 512*PSTRIDE;       // [256][2] reduced gate preacts
    float* hbuf = gbuf + 512;               // [2][2][128] double-buffered h

    int tid = threadIdx.x;
    int dir = blockIdx.y;
    unsigned rank; asm("mov.u32 %0, %%cluster_ctarank;" : "=r"(rank));
    unsigned peer = rank ^ 1u;
    int chunk = blockIdx.x >> 1;

    const float* Whh = dir ? WhhB : WhhF;
    float* Xout = (layer == 0) ? g_X1 : g_X2;
    const float* Gd = g_G + (size_t)dir*NROW*G4;

    // load W_hh slice (256 cols x 128 k) transposed into smem
    {
        int lc = tid >> 1, kh = (tid & 1)*64;
        int j = ((lc >> 6) << 7) + (int)rank*64 + (lc & 63);
        const float* wsrc = Whh + (size_t)j*HH + kh;
#pragma unroll
        for (int i = 0; i < 16; i++) {
            float4 v = *(const float4*)(wsrc + i*4);
            wt[(kh+i*4+0)*256 + lc] = v.x;
            wt[(kh+i*4+1)*256 + lc] = v.y;
            wt[(kh+i*4+2)*256 + lc] = v.z;
            wt[(kh+i*4+3)*256 + lc] = v.w;
        }
    }
    if (tid < 256) hbuf[tid] = 0.f;   // phase-0 h = 0 (both batch rows)
    __syncthreads();
    asm volatile("barrier.cluster.arrive.aligned;" ::: "memory");
    asm volatile("barrier.cluster.wait.aligned;"   ::: "memory");

    // matvec role
    int ct = tid & 31;                // col tile: cols [ct*8, ct*8+8)
    int kg = tid >> 5;                // k group : k in [kg*8, kg*8+8)
    // reduce role
    int colr = tid & 255, br = tid >> 8;
    int jgl  = ((colr >> 6) << 7) + (int)rank*64 + (colr & 63);
    int bglob_r = chunk*2 + br;
    int ctr = colr >> 3, cir = colr & 7;
    // update role (tid < 128)
    int bu = tid >> 6, nl = tid & 63;
    int ng = (int)rank*64 + nl;
    int bglob_u = chunk*2 + bu;
    float creg = 0.f;

    const float* wk = wt + (kg*8)*256 + ct*8;

    for (int s = 0; s < TT; ++s) {
        int t = dir ? (TT-1-s) : s;
        float gval = Gd[((size_t)t*BB + bglob_r)*G4 + jgl];   // prefetch, used after matvec
        const float* hb = hbuf + (s & 1)*256;

        float a00=0,a01=0,a02=0,a03=0,a04=0,a05=0,a06=0,a07=0;
        float a10=0,a11=0,a12=0,a13=0,a14=0,a15=0,a16=0,a17=0;
#pragma unroll
        for (int kk = 0; kk < 8; ++kk) {
            float4 w0 = *(const float4*)(wk + kk*256);
            float4 w1 = *(const float4*)(wk + kk*256 + 4);
            float h0 = hb[kg*8 + kk];
            float h1 = hb[128 + kg*8 + kk];
            a00+=w0.x*h0; a01+=w0.y*h0; a02+=w0.z*h0; a03+=w0.w*h0;
            a04+=w1.x*h0; a05+=w1.y*h0; a06+=w1.z*h0; a07+=w1.w*h0;
            a10+=w0.x*h1; a11+=w0.y*h1; a12+=w0.z*h1; a13+=w0.w*h1;
            a14+=w1.x*h1; a15+=w1.y*h1; a16+=w1.z*h1; a17+=w1.w*h1;
        }
        float* pp = part + tid*PSTRIDE;
        pp[0]=a00; pp[1]=a01; pp[2]=a02; pp[3]=a03;
        pp[4]=a04; pp[5]=a05; pp[6]=a06; pp[7]=a07;
        pp[8]=a10; pp[9]=a11; pp[10]=a12; pp[11]=a13;
        pp[12]=a14; pp[13]=a15; pp[14]=a16; pp[15]=a17;
        __syncthreads();
        {
            float ssum = gval;
            const float* pb = part + ctr*PSTRIDE + br*8 + cir;
#pragma unroll
            for (int kgi = 0; kgi < 16; ++kgi) ssum += pb[kgi*32*PSTRIDE];
            gbuf[colr*2 + br] = ssum;
        }
        __syncthreads();
        if (tid < 128) {
            float iv = gbuf[(      nl)*2 + bu];
            float fv = gbuf[( 64 + nl)*2 + bu];
            float gv = gbuf[(128 + nl)*2 + bu];
            float ov = gbuf[(192 + nl)*2 + bu];
            creg = sigf(fv)*creg + sigf(iv)*tanhf(gv);
            float h = sigf(ov)*tanhf(creg);
            int hoff = (((s+1) & 1)*2 + bu)*128 + ng;
            hbuf[hoff] = h;
            unsigned laddr = (unsigned)__cvta_generic_to_shared(&hbuf[hoff]);
            unsigned raddr;
            asm volatile("mapa.shared::cluster.u32 %0, %1, %2;" : "=r"(raddr) : "r"(laddr), "r"(peer));
            asm volatile("st.shared::cluster.f32 [%0], %1;" :: "r"(raddr), "f"(h) : "memory");
            Xout[((size_t)t*BB + bglob_u)*HD1 + dir*HH + ng] = h;
        }
        asm volatile("barrier.cluster.arrive.aligned;" ::: "memory");
        asm volatile("barrier.cluster.wait.aligned;"   ::: "memory");
    }
}

// ---------------- post: BN1+Linear+tanh+BN2+output-proj fused -> g_HL ----------------
__global__ void __launch_bounds__(256) k_post()
{
    __shared__ float as[16][64];
    __shared__ float bs[16][64];
    __shared__ float Hs[64][65];
    __shared__ float wh[2*HD2];
    __shared__ float hbb[2];
    int tid = threadIdx.x;
    int row0 = blockIdx.x*64;
    if (tid < 128) wh[tid] = g_Wh2[tid];
    if (tid < 2)   hbb[tid] = g_hb[tid];

    int lr = tid >> 2, kq = (tid & 3)*4;
    const float* arow = g_X2 + (size_t)(row0 + lr)*HD1;
    const float* wrow = g_Wp + lr*HD1;
    int rowgrp = tid >> 4, colgrp = tid & 15;
    float acc[4][4];
#pragma unroll
    for (int i = 0; i < 4; i++)
#pragma unroll
        for (int j = 0; j < 4; j++) acc[i][j] = 0.f;

    for (int kt = 0; kt < 16; ++kt) {
        int k0 = kt*16;
        float4 av = *(const float4*)(arow + k0 + kq);
        float4 bv = *(const float4*)(wrow + k0 + kq);
        __syncthreads();
        as[kq+0][lr]=av.x; as[kq+1][lr]=av.y; as[kq+2][lr]=av.z; as[kq+3][lr]=av.w;
        bs[kq+0][lr]=bv.x; bs[kq+1][lr]=bv.y; bs[kq+2][lr]=bv.z; bs[kq+3][lr]=bv.w;
        __syncthreads();
#pragma unroll
        for (int kk = 0; kk < 16; ++kk) {
            float4 a4 = *(const float4*)&as[kk][rowgrp*4];
            float4 b4 = *(const float4*)&bs[kk][colgrp*4];
            acc[0][0]+=a4.x*b4.x; acc[0][1]+=a4.x*b4.y; acc[0][2]+=a4.x*b4.z; acc[0][3]+=a4.x*b4.w;
            acc[1][0]+=a4.y*b4.x; acc[1][1]+=a4.y*b4.y; acc[1][2]+=a4.y*b4.z; acc[1][3]+=a4.y*b4.w;
            acc[2][0]+=a4.z*b4.x; acc[2][1]+=a4.z*b4.y; acc[2][2]+=a4.z*b4.z; acc[2][3]+=a4.z*b4.w;
            acc[3][0]+=a4.w*b4.x; acc[3][1]+=a4.w*b4.y; acc[3][2]+=a4.w*b4.z; acc[3][3]+=a4.w*b4.w;
        }
    }
    __syncthreads();
#pragma unroll
    for (int i = 0; i < 4; i++)
#pragma unroll
        for (int j = 0; j < 4; j++) {
            int c = colgrp*4 + j;
            Hs[rowgrp*4 + i][c] = tanhf(acc[i][j] + g_bp[c]);
        }
    __syncthreads();
    if (tid < 128) {
        int r = tid >> 1, k = tid & 1;
        float a = hbb[k];
#pragma unroll
        for (int c = 0; c < HD2; c++) a += Hs[r][c]*wh[k*HD2 + c];
        g_HL[(size_t)(row0 + r)*2 + k] = a;
    }
}

// ---------------- context scan: 64 independent chains ----------------
__global__ void k_ctx(const float* __restrict__ outw, float* __restrict__ out)
{
    int b = threadIdx.x;    // 0..63
    float W00=outw[0],  W01=outw[1],  W02=outw[2],  W03=outw[3];
    float W10=outw[68], W11=outw[69], W12=outw[70], W13=outw[71];
    float c0=0.f, c1=0.f, c2=0.f, c3=0.f;
    for (int t = 0; t < TT; ++t) {
        float h0 = g_HL[((size_t)t*BB + b)*2 + 0];
        float h1 = g_HL[((size_t)t*BB + b)*2 + 1];
        float l0 = h0 + c0*W00 + c1*W01 + c2*W02 + c3*W03;
        float l1 = h1 + c0*W10 + c1*W11 + c2*W12 + c3*W13;
        float m  = fmaxf(l0, l1);
        float lse = m + __logf(__expf(l0 - m) + __expf(l1 - m));
        float o0 = l0 - lse, o1 = l1 - lse;
        out[((size_t)b*TT + t)*2 + 0] = o0;
        out[((size_t)b*TT + t)*2 + 1] = o1;
        c0 = c2; c1 = c3; c2 = o0; c3 = o1;
    }
}

// ---------------- launch ----------------
extern "C" void kernel_launch(void* const* d_in, const int* in_sizes, int n_in,
                              void* d_out, int out_size)
{
    const float* x        = (const float*)d_in[0];
    const float* w_ih_l0  = (const float*)d_in[1];
    const float* w_hh_l0  = (const float*)d_in[2];
    const float* b_ih_l0  = (const float*)d_in[3];
    const float* b_hh_l0  = (const float*)d_in[4];
    const float* w_ih_l0r = (const float*)d_in[5];
    const float* w_hh_l0r = (const float*)d_in[6];
    const float* b_ih_l0r = (const float*)d_in[7];
    const float* b_hh_l0r = (const float*)d_in[8];
    const float* w_ih_l1  = (const float*)d_in[9];
    const float* w_hh_l1  = (const float*)d_in[10];
    const float* b_ih_l1  = (const float*)d_in[11];
    const float* b_hh_l1  = (const float*)d_in[12];
    const float* w_ih_l1r = (const float*)d_in[13];
    const float* w_hh_l1r = (const float*)d_in[14];
    const float* b_ih_l1r = (const float*)d_in[15];
    const float* b_hh_l1r = (const float*)d_in[16];
    const float* bn1_g    = (const float*)d_in[17];
    const float* bn1_b    = (const float*)d_in[18];
    const float* bn1_m    = (const float*)d_in[19];
    const float* bn1_v    = (const float*)d_in[20];
    const float* lin_w    = (const float*)d_in[21];
    const float* lin_b    = (const float*)d_in[22];
    const float* bn2_g    = (const float*)d_in[23];
    const float* bn2_b    = (const float*)d_in[24];
    const float* bn2_m    = (const float*)d_in[25];
    const float* bn2_v    = (const float*)d_in[26];
    const float* out_w    = (const float*)d_in[27];
    const float* out_b    = (const float*)d_in[28];

    size_t scan_smem = (size_t)SCAN_SMEM_FLOATS * sizeof(float);
    cudaFuncSetAttribute(k_scan, cudaFuncAttributeMaxDynamicSharedMemorySize, (int)scan_smem);

    k_prep<<<1, 256>>>(bn1_g, bn1_b, bn1_m, bn1_v, lin_w, lin_b,
                       bn2_g, bn2_b, bn2_m, bn2_v, out_w, out_b);

    dim3 gg(NROW/64, G4/64, 2);
    k_gemm<<<gg, 256>>>(x, w_ih_l0, b_ih_l0, b_hh_l0,
                           w_ih_l0r, b_ih_l0r, b_hh_l0r, DIN, 0);
    k_scan<<<dim3(64, 2), 512, scan_smem>>>(w_hh_l0, w_hh_l0r, 0);

    k_gemm<<<gg, 256>>>(x, w_ih_l1, b_ih_l1, b_hh_l1,
                           w_ih_l1r, b_ih_l1r, b_hh_l1r, HD1, 1);
    k_scan<<<dim3(64, 2), 512, scan_smem>>>(w_hh_l1, w_hh_l1r, 1);

    k_post<<<NROW/64, 256>>>();
    k_ctx<<<1, 64>>>(out_w, (float*)d_out);
}

// round 3
// speedup vs baseline: 1.2441x; 1.2441x over previous
#include <cuda_runtime.h>
#include <cstdint>

#define TT   1024
#define BB   64
#define DIN  400
#define HH   128
#define G4   512
#define HD1  256
#define HD2  64
#define NROW (TT*BB)

// ---------------- scratch (device globals; no runtime allocation) ----------------
__device__ float g_G  [(size_t)2*NROW*G4];   // gate preactivations, both dirs
__device__ float g_X1 [(size_t)NROW*HD1];    // layer0 output [t][b][256]
__device__ float g_X2 [(size_t)NROW*HD1];    // layer1 output [t][b][256]
__device__ float g_HL [(size_t)NROW*2];      // precomputed h-part of logits
__device__ float g_Wp [HD2*HD1];             // BN1-folded linear weight
__device__ float g_bp [HD2];                 // BN1-folded linear bias
__device__ float g_Wh2[2*HD2];               // BN2-folded output weight (h part)
__device__ float g_hb [2];                   // BN2-folded output bias

// ---------------- prep: fold BN1/BN2 into linear / output weights ----------------
__global__ void k_prep(const float* bn1g, const float* bn1b, const float* bn1m, const float* bn1v,
                       const float* linw, const float* linb,
                       const float* bn2g, const float* bn2b, const float* bn2m, const float* bn2v,
                       const float* outw, const float* outb) {
    __shared__ float s1[HD1], t1[HD1], s2[HD2], t2[HD2];
    int tid = threadIdx.x;
    if (tid < HD1) { float s = bn1g[tid]*rsqrtf(bn1v[tid]+1e-5f); s1[tid]=s; t1[tid]=bn1b[tid]-bn1m[tid]*s; }
    if (tid < HD2) { float s = bn2g[tid]*rsqrtf(bn2v[tid]+1e-5f); s2[tid]=s; t2[tid]=bn2b[tid]-bn2m[tid]*s; }
    __syncthreads();
    for (int i = tid; i < HD2*HD1; i += blockDim.x) g_Wp[i] = linw[i]*s1[i & (HD1-1)];
    if (tid < HD2) {
        float a = linb[tid];
        for (int j = 0; j < HD1; j++) a += t1[j]*linw[tid*HD1+j];
        g_bp[tid] = a;
    }
    if (tid < 2*HD2) { int k = tid>>6, c = tid&63; g_Wh2[tid] = outw[k*68+4+c]*s2[c]; }
    if (tid < 2) {
        float a = outb[tid];
        for (int c = 0; c < HD2; c++) a += t2[c]*outw[tid*68+4+c];
        g_hb[tid] = a;
    }
}

// ---------------- tf32 helpers ----------------
__device__ __forceinline__ unsigned f2tf(float f) {
    unsigned r; asm("cvt.rna.tf32.f32 %0, %1;" : "=r"(r) : "f"(f)); return r;
}
__device__ __forceinline__ void mma_tf32(float* c, unsigned a0, unsigned a1, unsigned a2, unsigned a3,
                                         unsigned b0, unsigned b1) {
    asm volatile("mma.sync.aligned.m16n8k8.row.col.f32.tf32.tf32.f32 "
                 "{%0,%1,%2,%3}, {%4,%5,%6,%7}, {%8,%9}, {%0,%1,%2,%3};"
                 : "+f"(c[0]), "+f"(c[1]), "+f"(c[2]), "+f"(c[3])
                 : "r"(a0), "r"(a1), "r"(a2), "r"(a3), "r"(b0), "r"(b1));
}

// ---------------- input-projection GEMM (tensor cores, tf32) ----------------
// C[65536 x 512] = A[65536 x K] * W^T + bias, per dir. CTA tile 128x128, 8 warps.
#define APAD 20
#define BPAD 136
__global__ void __launch_bounds__(256) k_gemm(
    const float* __restrict__ x,
    const float* __restrict__ Wf, const float* __restrict__ bif, const float* __restrict__ bhf,
    const float* __restrict__ Wr, const float* __restrict__ bir, const float* __restrict__ bhr,
    int Kdim, int layer)
{
    __shared__ unsigned As[2][128][APAD];
    __shared__ unsigned Bs[2][16][BPAD];

    int tid  = threadIdx.x;
    int row0 = blockIdx.x*128, col0 = blockIdx.y*128;
    int dir  = blockIdx.z;
    const float* W  = dir ? Wr  : Wf;
    const float* bi = dir ? bir : bif;
    const float* bh = dir ? bhr : bhf;

    // ---- load-role precompute ----
    const float* pA[2]; int sA[2];
    const float* pB[2]; int sB[2];
#pragma unroll
    for (int i = 0; i < 2; i++) {
        int t = tid + i*256;
        int rA = t >> 2, qA = t & 3;
        int r = row0 + rA;
        if (layer == 0) { int tt = r >> 6, b = r & 63; pA[i] = x + ((size_t)b*TT + tt)*DIN + qA*4; }
        else            { pA[i] = g_X1 + (size_t)r*HD1 + qA*4; }
        sA[i] = rA*APAD + qA*4;
        int qB = t >> 7, colB = t & 127;
        pB[i] = W + (size_t)(col0 + colB)*Kdim + qB*4;
        sB[i] = qB*4*BPAD + colB;          // rows qB*4..qB*4+3, col colB
    }

    // ---- mma-role precompute ----
    int warp = tid >> 5, lane = tid & 31;
    int wm = warp >> 1, wn = warp & 1;     // 4x2 warp grid
    int l4 = lane >> 2, lq = lane & 3;
    int am0 = wm*32;                       // warp M base (local)
    int bn0 = wn*64;                       // warp N base (local)

    float acc[2][8][4];
#pragma unroll
    for (int mt = 0; mt < 2; mt++)
#pragma unroll
        for (int nt = 0; nt < 8; nt++)
#pragma unroll
            for (int j = 0; j < 4; j++) acc[mt][nt][j] = 0.f;

    int nkt = Kdim >> 4;

    // prologue: stage 0
    {
        float4 ra0 = *(const float4*)(pA[0]);
        float4 ra1 = *(const float4*)(pA[1]);
        float4 rb0 = *(const float4*)(pB[0]);
        float4 rb1 = *(const float4*)(pB[1]);
        unsigned* A0 = &As[0][0][0];
        unsigned* B0 = &Bs[0][0][0];
        *(uint4*)(A0 + sA[0]) = make_uint4(f2tf(ra0.x), f2tf(ra0.y), f2tf(ra0.z), f2tf(ra0.w));
        *(uint4*)(A0 + sA[1]) = make_uint4(f2tf(ra1.x), f2tf(ra1.y), f2tf(ra1.z), f2tf(ra1.w));
        B0[sB[0]+0*BPAD]=f2tf(rb0.x); B0[sB[0]+1*BPAD]=f2tf(rb0.y); B0[sB[0]+2*BPAD]=f2tf(rb0.z); B0[sB[0]+3*BPAD]=f2tf(rb0.w);
        B0[sB[1]+0*BPAD]=f2tf(rb1.x); B0[sB[1]+1*BPAD]=f2tf(rb1.y); B0[sB[1]+2*BPAD]=f2tf(rb1.z); B0[sB[1]+3*BPAD]=f2tf(rb1.w);
    }
    __syncthreads();

    for (int kt = 0; kt < nkt; ++kt) {
        int cur = kt & 1, nxt = cur ^ 1;
        float4 ra0, ra1, rb0, rb1;
        bool more = (kt + 1 < nkt);
        if (more) {
            int k0 = (kt + 1) * 16;
            ra0 = *(const float4*)(pA[0] + k0);
            ra1 = *(const float4*)(pA[1] + k0);
            rb0 = *(const float4*)(pB[0] + k0);
            rb1 = *(const float4*)(pB[1] + k0);
        }
        const unsigned* Ac = &As[cur][0][0];
        const unsigned* Bc = &Bs[cur][0][0];
#pragma unroll
        for (int kh = 0; kh < 16; kh += 8) {
            unsigned bf[8][2];
#pragma unroll
            for (int nt = 0; nt < 8; nt++) {
                bf[nt][0] = Bc[(kh + lq)*BPAD + bn0 + nt*8 + l4];
                bf[nt][1] = Bc[(kh + lq + 4)*BPAD + bn0 + nt*8 + l4];
            }
#pragma unroll
            for (int mt = 0; mt < 2; mt++) {
                int mr = am0 + mt*16 + l4;
                unsigned a0 = Ac[mr*APAD + kh + lq];
                unsigned a1 = Ac[(mr+8)*APAD + kh + lq];
                unsigned a2 = Ac[mr*APAD + kh + lq + 4];
                unsigned a3 = Ac[(mr+8)*APAD + kh + lq + 4];
#pragma unroll
                for (int nt = 0; nt < 8; nt++)
                    mma_tf32(acc[mt][nt], a0, a1, a2, a3, bf[nt][0], bf[nt][1]);
            }
        }
        __syncthreads();
        if (more) {
            unsigned* An = &As[nxt][0][0];
            unsigned* Bn = &Bs[nxt][0][0];
            *(uint4*)(An + sA[0]) = make_uint4(f2tf(ra0.x), f2tf(ra0.y), f2tf(ra0.z), f2tf(ra0.w));
            *(uint4*)(An + sA[1]) = make_uint4(f2tf(ra1.x), f2tf(ra1.y), f2tf(ra1.z), f2tf(ra1.w));
            Bn[sB[0]+0*BPAD]=f2tf(rb0.x); Bn[sB[0]+1*BPAD]=f2tf(rb0.y); Bn[sB[0]+2*BPAD]=f2tf(rb0.z); Bn[sB[0]+3*BPAD]=f2tf(rb0.w);
            Bn[sB[1]+0*BPAD]=f2tf(rb1.x); Bn[sB[1]+1*BPAD]=f2tf(rb1.y); Bn[sB[1]+2*BPAD]=f2tf(rb1.z); Bn[sB[1]+3*BPAD]=f2tf(rb1.w);
        }
        __syncthreads();
    }

    // ---- epilogue: bias + store ----
    float* Cb = g_G + (size_t)dir*NROW*G4;
#pragma unroll
    for (int mt = 0; mt < 2; mt++) {
        int r = row0 + am0 + mt*16 + l4;
#pragma unroll
        for (int nt = 0; nt < 8; nt++) {
            int c = col0 + bn0 + nt*8 + 2*lq;
            float2 b1v = *(const float2*)(bi + c);
            float2 b2v = *(const float2*)(bh + c);
            float bx = b1v.x + b2v.x, by = b1v.y + b2v.y;
            float2 v0; v0.x = acc[mt][nt][0] + bx; v0.y = acc[mt][nt][1] + by;
            float2 v1; v1.x = acc[mt][nt][2] + bx; v1.y = acc[mt][nt][3] + by;
            *(float2*)(Cb + (size_t)r*G4 + c)     = v0;
            *(float2*)(Cb + (size_t)(r+8)*G4 + c) = v1;
        }
    }
}

// ---------------- recurrent scan: cluster of 2 CTAs, n-split, batch-chunked ----------------
#define PSTRIDE 20
#define SCAN_SMEM_FLOATS (32768 + 512*PSTRIDE + 512 + 512)

__device__ __forceinline__ float sigf(float x) { return 1.f/(1.f + __expf(-x)); }

__global__ __launch_bounds__(512, 1) __cluster_dims__(2, 1, 1)
void k_scan(const float* __restrict__ WhhF, const float* __restrict__ WhhB, int layer)
{
    extern __shared__ float sm[];
    float* wt   = sm;                       // [128][256] weights, k-major
    float* part = sm + 32768;               // [512][PSTRIDE] partials
    float* gbuf = part + 512*PSTRIDE;       // [256][2] reduced gate preacts
    float* hbuf = gbuf + 512;               // [2][2][128] double-buffered h

    int tid = threadIdx.x;
    int dir = blockIdx.y;
    unsigned rank; asm("mov.u32 %0, %%cluster_ctarank;" : "=r"(rank));
    unsigned peer = rank ^ 1u;
    int chunk = blockIdx.x >> 1;

    const float* Whh = dir ? WhhB : WhhF;
    float* Xout = (layer == 0) ? g_X1 : g_X2;
    const float* Gd = g_G + (size_t)dir*NROW*G4;

    {
        int lc = tid >> 1, kh = (tid & 1)*64;
        int j = ((lc >> 6) << 7) + (int)rank*64 + (lc & 63);
        const float* wsrc = Whh + (size_t)j*HH + kh;
#pragma unroll
        for (int i = 0; i < 16; i++) {
            float4 v = *(const float4*)(wsrc + i*4);
            wt[(kh+i*4+0)*256 + lc] = v.x;
            wt[(kh+i*4+1)*256 + lc] = v.y;
            wt[(kh+i*4+2)*256 + lc] = v.z;
            wt[(kh+i*4+3)*256 + lc] = v.w;
        }
    }
    if (tid < 256) hbuf[tid] = 0.f;
    __syncthreads();
    asm volatile("barrier.cluster.arrive.aligned;" ::: "memory");
    asm volatile("barrier.cluster.wait.aligned;"   ::: "memory");

    int ct = tid & 31;
    int kg = tid >> 5;
    int colr = tid & 255, br = tid >> 8;
    int jgl  = ((colr >> 6) << 7) + (int)rank*64 + (colr & 63);
    int bglob_r = chunk*2 + br;
    int ctr = colr >> 3, cir = colr & 7;
    int bu = tid >> 6, nl = tid & 63;
    int ng = (int)rank*64 + nl;
    int bglob_u = chunk*2 + bu;
    float creg = 0.f;

    const float* wk = wt + (kg*8)*256 + ct*8;

    for (int s = 0; s < TT; ++s) {
        int t = dir ? (TT-1-s) : s;
        float gval = Gd[((size_t)t*BB + bglob_r)*G4 + jgl];
        const float* hb = hbuf + (s & 1)*256;

        float a00=0,a01=0,a02=0,a03=0,a04=0,a05=0,a06=0,a07=0;
        float a10=0,a11=0,a12=0,a13=0,a14=0,a15=0,a16=0,a17=0;
#pragma unroll
        for (int kk = 0; kk < 8; ++kk) {
            float4 w0 = *(const float4*)(wk + kk*256);
            float4 w1 = *(const float4*)(wk + kk*256 + 4);
            float h0 = hb[kg*8 + kk];
            float h1 = hb[128 + kg*8 + kk];
            a00+=w0.x*h0; a01+=w0.y*h0; a02+=w0.z*h0; a03+=w0.w*h0;
            a04+=w1.x*h0; a05+=w1.y*h0; a06+=w1.z*h0; a07+=w1.w*h0;
            a10+=w0.x*h1; a11+=w0.y*h1; a12+=w0.z*h1; a13+=w0.w*h1;
            a14+=w1.x*h1; a15+=w1.y*h1; a16+=w1.z*h1; a17+=w1.w*h1;
        }
        float* pp = part + tid*PSTRIDE;
        pp[0]=a00; pp[1]=a01; pp[2]=a02; pp[3]=a03;
        pp[4]=a04; pp[5]=a05; pp[6]=a06; pp[7]=a07;
        pp[8]=a10; pp[9]=a11; pp[10]=a12; pp[11]=a13;
        pp[12]=a14; pp[13]=a15; pp[14]=a16; pp[15]=a17;
        __syncthreads();
        {
            float ssum = gval;
            const float* pb = part + ctr*PSTRIDE + br*8 + cir;
#pragma unroll
            for (int kgi = 0; kgi < 16; ++kgi) ssum += pb[kgi*32*PSTRIDE];
            gbuf[colr*2 + br] = ssum;
        }
        __syncthreads();
        if (tid < 128) {
            float iv = gbuf[(      nl)*2 + bu];
            float fv = gbuf[( 64 + nl)*2 + bu];
            float gv = gbuf[(128 + nl)*2 + bu];
            float ov = gbuf[(192 + nl)*2 + bu];
            creg = sigf(fv)*creg + sigf(iv)*tanhf(gv);
            float h = sigf(ov)*tanhf(creg);
            int hoff = (((s+1) & 1)*2 + bu)*128 + ng;
            hbuf[hoff] = h;
            unsigned laddr = (unsigned)__cvta_generic_to_shared(&hbuf[hoff]);
            unsigned raddr;
            asm volatile("mapa.shared::cluster.u32 %0, %1, %2;" : "=r"(raddr) : "r"(laddr), "r"(peer));
            asm volatile("st.shared::cluster.f32 [%0], %1;" :: "r"(raddr), "f"(h) : "memory");
            Xout[((size_t)t*BB + bglob_u)*HD1 + dir*HH + ng] = h;
        }
        asm volatile("barrier.cluster.arrive.aligned;" ::: "memory");
        asm volatile("barrier.cluster.wait.aligned;"   ::: "memory");
    }
}

// ---------------- post: BN1+Linear+tanh+BN2+output-proj fused -> g_HL ----------------
__global__ void __launch_bounds__(256) k_post()
{
    __shared__ float as[16][64];
    __shared__ float bs[16][64];
    __shared__ float Hs[64][65];
    __shared__ float wh[2*HD2];
    __shared__ float hbb[2];
    int tid = threadIdx.x;
    int row0 = blockIdx.x*64;
    if (tid < 128) wh[tid] = g_Wh2[tid];
    if (tid < 2)   hbb[tid] = g_hb[tid];

    int lr = tid >> 2, kq = (tid & 3)*4;
    const float* arow = g_X2 + (size_t)(row0 + lr)*HD1;
    const float* wrow = g_Wp + lr*HD1;
    int rowgrp = tid >> 4, colgrp = tid & 15;
    float acc[4][4];
#pragma unroll
    for (int i = 0; i < 4; i++)
#pragma unroll
        for (int j = 0; j < 4; j++) acc[i][j] = 0.f;

    for (int kt = 0; kt < 16; ++kt) {
        int k0 = kt*16;
        float4 av = *(const float4*)(arow + k0 + kq);
        float4 bv = *(const float4*)(wrow + k0 + kq);
        __syncthreads();
        as[kq+0][lr]=av.x; as[kq+1][lr]=av.y; as[kq+2][lr]=av.z; as[kq+3][lr]=av.w;
        bs[kq+0][lr]=bv.x; bs[kq+1][lr]=bv.y; bs[kq+2][lr]=bv.z; bs[kq+3][lr]=bv.w;
        __syncthreads();
#pragma unroll
        for (int kk = 0; kk < 16; ++kk) {
            float4 a4 = *(const float4*)&as[kk][rowgrp*4];
            float4 b4 = *(const float4*)&bs[kk][colgrp*4];
            acc[0][0]+=a4.x*b4.x; acc[0][1]+=a4.x*b4.y; acc[0][2]+=a4.x*b4.z; acc[0][3]+=a4.x*b4.w;
            acc[1][0]+=a4.y*b4.x; acc[1][1]+=a4.y*b4.y; acc[1][2]+=a4.y*b4.z; acc[1][3]+=a4.y*b4.w;
            acc[2][0]+=a4.z*b4.x; acc[2][1]+=a4.z*b4.y; acc[2][2]+=a4.z*b4.z; acc[2][3]+=a4.z*b4.w;
            acc[3][0]+=a4.w*b4.x; acc[3][1]+=a4.w*b4.y; acc[3][2]+=a4.w*b4.z; acc[3][3]+=a4.w*b4.w;
        }
    }
    __syncthreads();
#pragma unroll
    for (int i = 0; i < 4; i++)
#pragma unroll
        for (int j = 0; j < 4; j++) {
            int c = colgrp*4 + j;
            Hs[rowgrp*4 + i][c] = tanhf(acc[i][j] + g_bp[c]);
        }
    __syncthreads();
    if (tid < 128) {
        int r = tid >> 1, k = tid & 1;
        float a = hbb[k];
#pragma unroll
        for (int c = 0; c < HD2; c++) a += Hs[r][c]*wh[k*HD2 + c];
        g_HL[(size_t)(row0 + r)*2 + k] = a;
    }
}

// ---------------- context scan: 64 independent chains ----------------
__global__ void k_ctx(const float* __restrict__ outw, float* __restrict__ out)
{
    int b = threadIdx.x;
    float W00=outw[0],  W01=outw[1],  W02=outw[2],  W03=outw[3];
    float W10=outw[68], W11=outw[69], W12=outw[70], W13=outw[71];
    float c0=0.f, c1=0.f, c2=0.f, c3=0.f;
    for (int t = 0; t < TT; ++t) {
        float h0 = g_HL[((size_t)t*BB + b)*2 + 0];
        float h1 = g_HL[((size_t)t*BB + b)*2 + 1];
        float l0 = h0 + c0*W00 + c1*W01 + c2*W02 + c3*W03;
        float l1 = h1 + c0*W10 + c1*W11 + c2*W12 + c3*W13;
        float m  = fmaxf(l0, l1);
        float lse = m + __logf(__expf(l0 - m) + __expf(l1 - m));
        float o0 = l0 - lse, o1 = l1 - lse;
        out[((size_t)b*TT + t)*2 + 0] = o0;
        out[((size_t)b*TT + t)*2 + 1] = o1;
        c0 = c2; c1 = c3; c2 = o0; c3 = o1;
    }
}

// ---------------- launch ----------------
extern "C" void kernel_launch(void* const* d_in, const int* in_sizes, int n_in,
                              void* d_out, int out_size)
{
    const float* x        = (const float*)d_in[0];
    const float* w_ih_l0  = (const float*)d_in[1];
    const float* w_hh_l0  = (const float*)d_in[2];
    const float* b_ih_l0  = (const float*)d_in[3];
    const float* b_hh_l0  = (const float*)d_in[4];
    const float* w_ih_l0r = (const float*)d_in[5];
    const float* w_hh_l0r = (const float*)d_in[6];
    const float* b_ih_l0r = (const float*)d_in[7];
    const float* b_hh_l0r = (const float*)d_in[8];
    const float* w_ih_l1  = (const float*)d_in[9];
    const float* w_hh_l1  = (const float*)d_in[10];
    const float* b_ih_l1  = (const float*)d_in[11];
    const float* b_hh_l1  = (const float*)d_in[12];
    const float* w_ih_l1r = (const float*)d_in[13];
    const float* w_hh_l1r = (const float*)d_in[14];
    const float* b_ih_l1r = (const float*)d_in[15];
    const float* b_hh_l1r = (const float*)d_in[16];
    const float* bn1_g    = (const float*)d_in[17];
    const float* bn1_b    = (const float*)d_in[18];
    const float* bn1_m    = (const float*)d_in[19];
    const float* bn1_v    = (const float*)d_in[20];
    const float* lin_w    = (const float*)d_in[21];
    const float* lin_b    = (const float*)d_in[22];
    const float* bn2_g    = (const float*)d_in[23];
    const float* bn2_b    = (const float*)d_in[24];
    const float* bn2_m    = (const float*)d_in[25];
    const float* bn2_v    = (const float*)d_in[26];
    const float* out_w    = (const float*)d_in[27];
    const float* out_b    = (const float*)d_in[28];

    size_t scan_smem = (size_t)SCAN_SMEM_FLOATS * sizeof(float);
    cudaFuncSetAttribute(k_scan, cudaFuncAttributeMaxDynamicSharedMemorySize, (int)scan_smem);

    k_prep<<<1, 256>>>(bn1_g, bn1_b, bn1_m, bn1_v, lin_w, lin_b,
                       bn2_g, bn2_b, bn2_m, bn2_v, out_w, out_b);

    dim3 gg(NROW/128, G4/128, 2);
    k_gemm<<<gg, 256>>>(x, w_ih_l0, b_ih_l0, b_hh_l0,
                           w_ih_l0r, b_ih_l0r, b_hh_l0r, DIN, 0);
    k_scan<<<dim3(64, 2), 512, scan_smem>>>(w_hh_l0, w_hh_l0r, 0);

    k_gemm<<<gg, 256>>>(x, w_ih_l1, b_ih_l1, b_hh_l1,
                           w_ih_l1r, b_ih_l1r, b_hh_l1r, HD1, 1);
    k_scan<<<dim3(64, 2), 512, scan_smem>>>(w_hh_l1, w_hh_l1r, 1);

    k_post<<<NROW/64, 256>>>();
    k_ctx<<<1, 64>>>(out_w, (float*)d_out);
}

// round 4
// speedup vs baseline: 1.9022x; 1.5290x over previous
#include <cuda_runtime.h>
#include <cstdint>

#define TT   1024
#define BB   64
#define DIN  400
#define HH   128
#define G4   512
#define HD1  256
#define HD2  64
#define NROW (TT*BB)

// ---------------- scratch (device globals; no runtime allocation) ----------------
__device__ float g_G  [(size_t)2*NROW*G4];   // gate preactivations, both dirs
__device__ float g_X1 [(size_t)NROW*HD1];    // layer0 output [t][b][256]
__device__ float g_X2 [(size_t)NROW*HD1];    // layer1 output [t][b][256]
__device__ float g_HL [(size_t)NROW*2];      // precomputed h-part of logits
__device__ float g_Wp [HD2*HD1];             // BN1-folded linear weight
__device__ float g_bp [HD2];                 // BN1-folded linear bias
__device__ float g_Wh2[2*HD2];               // BN2-folded output weight (h part)
__device__ float g_hb [2];                   // BN2-folded output bias

// ---------------- prep: fold BN1/BN2 into linear / output weights ----------------
__global__ void k_prep(const float* bn1g, const float* bn1b, const float* bn1m, const float* bn1v,
                       const float* linw, const float* linb,
                       const float* bn2g, const float* bn2b, const float* bn2m, const float* bn2v,
                       const float* outw, const float* outb) {
    __shared__ float s1[HD1], t1[HD1], s2[HD2], t2[HD2];
    int tid = threadIdx.x;
    if (tid < HD1) { float s = bn1g[tid]*rsqrtf(bn1v[tid]+1e-5f); s1[tid]=s; t1[tid]=bn1b[tid]-bn1m[tid]*s; }
    if (tid < HD2) { float s = bn2g[tid]*rsqrtf(bn2v[tid]+1e-5f); s2[tid]=s; t2[tid]=bn2b[tid]-bn2m[tid]*s; }
    __syncthreads();
    for (int i = tid; i < HD2*HD1; i += blockDim.x) g_Wp[i] = linw[i]*s1[i & (HD1-1)];
    if (tid < HD2) {
        float a = linb[tid];
        for (int j = 0; j < HD1; j++) a += t1[j]*linw[tid*HD1+j];
        g_bp[tid] = a;
    }
    if (tid < 2*HD2) { int k = tid>>6, c = tid&63; g_Wh2[tid] = outw[k*68+4+c]*s2[c]; }
    if (tid < 2) {
        float a = outb[tid];
        for (int c = 0; c < HD2; c++) a += t2[c]*outw[tid*68+4+c];
        g_hb[tid] = a;
    }
}

// ---------------- tf32 helpers ----------------
__device__ __forceinline__ unsigned f2tf(float f) {
    unsigned r; asm("cvt.rna.tf32.f32 %0, %1;" : "=r"(r) : "f"(f)); return r;
}
__device__ __forceinline__ void mma_tf32(float* c, unsigned a0, unsigned a1, unsigned a2, unsigned a3,
                                         unsigned b0, unsigned b1) {
    asm volatile("mma.sync.aligned.m16n8k8.row.col.f32.tf32.tf32.f32 "
                 "{%0,%1,%2,%3}, {%4,%5,%6,%7}, {%8,%9}, {%0,%1,%2,%3};"
                 : "+f"(c[0]), "+f"(c[1]), "+f"(c[2]), "+f"(c[3])
                 : "r"(a0), "r"(a1), "r"(a2), "r"(a3), "r"(b0), "r"(b1));
}

// ---------------- f32x2 packed helpers ----------------
__device__ __forceinline__ unsigned long long pk2(float a, float b) {
    unsigned long long r; asm("mov.b64 %0, {%1,%2};" : "=l"(r) : "f"(a), "f"(b)); return r;
}
__device__ __forceinline__ unsigned long long ff2(unsigned long long a, unsigned long long b,
                                                  unsigned long long c) {
    unsigned long long d;
    asm("fma.rn.f32x2 %0, %1, %2, %3;" : "=l"(d) : "l"(a), "l"(b), "l"(c));
    return d;
}
__device__ __forceinline__ void up2(unsigned long long a, float& x, float& y) {
    asm("mov.b64 {%0,%1}, %2;" : "=f"(x), "=f"(y) : "l"(a));
}

// ---------------- input-projection GEMM (tensor cores, tf32) ----------------
#define APAD 20
#define BPAD 136
__global__ void __launch_bounds__(256) k_gemm(
    const float* __restrict__ x,
    const float* __restrict__ Wf, const float* __restrict__ bif, const float* __restrict__ bhf,
    const float* __restrict__ Wr, const float* __restrict__ bir, const float* __restrict__ bhr,
    int Kdim, int layer)
{
    __shared__ unsigned As[2][128][APAD];
    __shared__ unsigned Bs[2][16][BPAD];

    int tid  = threadIdx.x;
    int row0 = blockIdx.x*128, col0 = blockIdx.y*128;
    int dir  = blockIdx.z;
    const float* W  = dir ? Wr  : Wf;
    const float* bi = dir ? bir : bif;
    const float* bh = dir ? bhr : bhf;

    const float* pA[2]; int sA[2];
    const float* pB[2]; int sB[2];
#pragma unroll
    for (int i = 0; i < 2; i++) {
        int t = tid + i*256;
        int rA = t >> 2, qA = t & 3;
        int r = row0 + rA;
        if (layer == 0) { int tt = r >> 6, b = r & 63; pA[i] = x + ((size_t)b*TT + tt)*DIN + qA*4; }
        else            { pA[i] = g_X1 + (size_t)r*HD1 + qA*4; }
        sA[i] = rA*APAD + qA*4;
        int qB = t >> 7, colB = t & 127;
        pB[i] = W + (size_t)(col0 + colB)*Kdim + qB*4;
        sB[i] = qB*4*BPAD + colB;
    }

    int warp = tid >> 5, lane = tid & 31;
    int wm = warp >> 1, wn = warp & 1;
    int l4 = lane >> 2, lq = lane & 3;
    int am0 = wm*32;
    int bn0 = wn*64;

    float acc[2][8][4];
#pragma unroll
    for (int mt = 0; mt < 2; mt++)
#pragma unroll
        for (int nt = 0; nt < 8; nt++)
#pragma unroll
            for (int j = 0; j < 4; j++) acc[mt][nt][j] = 0.f;

    int nkt = Kdim >> 4;

    {
        float4 ra0 = *(const float4*)(pA[0]);
        float4 ra1 = *(const float4*)(pA[1]);
        float4 rb0 = *(const float4*)(pB[0]);
        float4 rb1 = *(const float4*)(pB[1]);
        unsigned* A0 = &As[0][0][0];
        unsigned* B0 = &Bs[0][0][0];
        *(uint4*)(A0 + sA[0]) = make_uint4(f2tf(ra0.x), f2tf(ra0.y), f2tf(ra0.z), f2tf(ra0.w));
        *(uint4*)(A0 + sA[1]) = make_uint4(f2tf(ra1.x), f2tf(ra1.y), f2tf(ra1.z), f2tf(ra1.w));
        B0[sB[0]+0*BPAD]=f2tf(rb0.x); B0[sB[0]+1*BPAD]=f2tf(rb0.y); B0[sB[0]+2*BPAD]=f2tf(rb0.z); B0[sB[0]+3*BPAD]=f2tf(rb0.w);
        B0[sB[1]+0*BPAD]=f2tf(rb1.x); B0[sB[1]+1*BPAD]=f2tf(rb1.y); B0[sB[1]+2*BPAD]=f2tf(rb1.z); B0[sB[1]+3*BPAD]=f2tf(rb1.w);
    }
    __syncthreads();

    for (int kt = 0; kt < nkt; ++kt) {
        int cur = kt & 1, nxt = cur ^ 1;
        float4 ra0, ra1, rb0, rb1;
        bool more = (kt + 1 < nkt);
        if (more) {
            int k0 = (kt + 1) * 16;
            ra0 = *(const float4*)(pA[0] + k0);
            ra1 = *(const float4*)(pA[1] + k0);
            rb0 = *(const float4*)(pB[0] + k0);
            rb1 = *(const float4*)(pB[1] + k0);
        }
        const unsigned* Ac = &As[cur][0][0];
        const unsigned* Bc = &Bs[cur][0][0];
#pragma unroll
        for (int kh = 0; kh < 16; kh += 8) {
            unsigned bf[8][2];
#pragma unroll
            for (int nt = 0; nt < 8; nt++) {
                bf[nt][0] = Bc[(kh + lq)*BPAD + bn0 + nt*8 + l4];
                bf[nt][1] = Bc[(kh + lq + 4)*BPAD + bn0 + nt*8 + l4];
            }
#pragma unroll
            for (int mt = 0; mt < 2; mt++) {
                int mr = am0 + mt*16 + l4;
                unsigned a0 = Ac[mr*APAD + kh + lq];
                unsigned a1 = Ac[(mr+8)*APAD + kh + lq];
                unsigned a2 = Ac[mr*APAD + kh + lq + 4];
                unsigned a3 = Ac[(mr+8)*APAD + kh + lq + 4];
#pragma unroll
                for (int nt = 0; nt < 8; nt++)
                    mma_tf32(acc[mt][nt], a0, a1, a2, a3, bf[nt][0], bf[nt][1]);
            }
        }
        __syncthreads();
        if (more) {
            unsigned* An = &As[nxt][0][0];
            unsigned* Bn = &Bs[nxt][0][0];
            *(uint4*)(An + sA[0]) = make_uint4(f2tf(ra0.x), f2tf(ra0.y), f2tf(ra0.z), f2tf(ra0.w));
            *(uint4*)(An + sA[1]) = make_uint4(f2tf(ra1.x), f2tf(ra1.y), f2tf(ra1.z), f2tf(ra1.w));
            Bn[sB[0]+0*BPAD]=f2tf(rb0.x); Bn[sB[0]+1*BPAD]=f2tf(rb0.y); Bn[sB[0]+2*BPAD]=f2tf(rb0.z); Bn[sB[0]+3*BPAD]=f2tf(rb0.w);
            Bn[sB[1]+0*BPAD]=f2tf(rb1.x); Bn[sB[1]+1*BPAD]=f2tf(rb1.y); Bn[sB[1]+2*BPAD]=f2tf(rb1.z); Bn[sB[1]+3*BPAD]=f2tf(rb1.w);
        }
        __syncthreads();
    }

    float* Cb = g_G + (size_t)dir*NROW*G4;
#pragma unroll
    for (int mt = 0; mt < 2; mt++) {
        int r = row0 + am0 + mt*16 + l4;
#pragma unroll
        for (int nt = 0; nt < 8; nt++) {
            int c = col0 + bn0 + nt*8 + 2*lq;
            float2 b1v = *(const float2*)(bi + c);
            float2 b2v = *(const float2*)(bh + c);
            float bx = b1v.x + b2v.x, by = b1v.y + b2v.y;
            float2 v0; v0.x = acc[mt][nt][0] + bx; v0.y = acc[mt][nt][1] + by;
            float2 v1; v1.x = acc[mt][nt][2] + bx; v1.y = acc[mt][nt][3] + by;
            *(float2*)(Cb + (size_t)r*G4 + c)     = v0;
            *(float2*)(Cb + (size_t)(r+8)*G4 + c) = v1;
        }
    }
}

// ---------------- recurrent scan: register-resident weights + f32x2 ----------------
// grid (64,2): 32 chunks x 2 ranks, 2 dirs; 512 threads; static smem ~36KB.
#define PCOL 256

__device__ __forceinline__ float sigf(float x) { return 1.f/(1.f + __expf(-x)); }

__global__ __launch_bounds__(512, 1) __cluster_dims__(2, 1, 1)
void k_scan(const float* __restrict__ WhhF, const float* __restrict__ WhhB, int layer)
{
    __shared__ float part[2*16*PCOL];     // [b][kg][col] 32KB
    __shared__ float gbuf[512];           // [256 col][2 b]
    __shared__ float hbuf[512];           // [2 phase][2 b][128]

    int tid = threadIdx.x;
    int dir = blockIdx.y;
    unsigned rank; asm("mov.u32 %0, %%cluster_ctarank;" : "=r"(rank));
    unsigned peer = rank ^ 1u;
    int chunk = blockIdx.x >> 1;

    const float* Whh = dir ? WhhB : WhhF;
    float* Xout = (layer == 0) ? g_X1 : g_X2;
    const float* Gd = g_G + (size_t)dir*NROW*G4;

    int kg = tid >> 5;                     // 0..15 : k in [kg*8, kg*8+8)
    int ct = tid & 31;                     // 0..31 : cols [ct*8, ct*8+8)

    // register-resident W_hh slice, packed f32x2 over k-pairs
    unsigned long long wq[32];
#pragma unroll
    for (int cc = 0; cc < 8; cc++) {
        int lc = ct*8 + cc;
        int j = ((lc >> 6) << 7) + (int)rank*64 + (lc & 63);
        const float* wr = Whh + (size_t)j*HH + kg*8;
        float4 v0 = *(const float4*)(wr);
        float4 v1 = *(const float4*)(wr + 4);
        wq[cc*4+0] = pk2(v0.x, v0.y);
        wq[cc*4+1] = pk2(v0.z, v0.w);
        wq[cc*4+2] = pk2(v1.x, v1.y);
        wq[cc*4+3] = pk2(v1.z, v1.w);
    }

    hbuf[tid] = 0.f;
    __syncthreads();
    asm volatile("barrier.cluster.arrive.aligned;" ::: "memory");
    asm volatile("barrier.cluster.wait.aligned;"   ::: "memory");

    // reduce role
    int colr = tid & 255, br = tid >> 8;
    int jgl  = ((colr >> 6) << 7) + (int)rank*64 + (colr & 63);
    int bglob_r = chunk*2 + br;
    // update role (tid < 128)
    int bu = tid >> 6, nl = tid & 63;
    int ng = (int)rank*64 + nl;
    int bglob_u = chunk*2 + bu;
    float creg = 0.f;

    unsigned hbuf_r;
    {
        unsigned hl = (unsigned)__cvta_generic_to_shared(hbuf);
        asm("mapa.shared::cluster.u32 %0, %1, %2;" : "=r"(hbuf_r) : "r"(hl), "r"(peer));
    }

    long long gstep = dir ? -(long long)(BB*G4) : (long long)(BB*G4);
    const float* gptr = Gd + ((size_t)(dir ? TT-1 : 0)*BB + bglob_r)*G4 + jgl;
    float gcur = __ldg(gptr);

    float* ps0 = part + kg*PCOL + ct*8;
    float* ps1 = ps0 + 16*PCOL;
    const float* pred = part + br*16*PCOL + colr;

    for (int s = 0; s < TT; ++s) {
        float gnext = 0.f;
        if (s + 1 < TT) { gptr += gstep; gnext = __ldg(gptr); }

        // ---- matvec: broadcast h loads, register weights, f32x2 FMAs ----
        const float* hb = hbuf + (s & 1)*256;
        float4 ha0 = *(const float4*)(hb + kg*8);
        float4 ha1 = *(const float4*)(hb + kg*8 + 4);
        float4 hc0 = *(const float4*)(hb + 128 + kg*8);
        float4 hc1 = *(const float4*)(hb + 128 + kg*8 + 4);
        unsigned long long hp0[4], hp1[4];
        hp0[0]=pk2(ha0.x,ha0.y); hp0[1]=pk2(ha0.z,ha0.w); hp0[2]=pk2(ha1.x,ha1.y); hp0[3]=pk2(ha1.z,ha1.w);
        hp1[0]=pk2(hc0.x,hc0.y); hp1[1]=pk2(hc0.z,hc0.w); hp1[2]=pk2(hc1.x,hc1.y); hp1[3]=pk2(hc1.z,hc1.w);
        float r0[8], r1[8];
#pragma unroll
        for (int cc = 0; cc < 8; cc++) {
            unsigned long long a0 = 0ull, a1 = 0ull;
#pragma unroll
            for (int kp = 0; kp < 4; kp++) {
                a0 = ff2(wq[cc*4+kp], hp0[kp], a0);
                a1 = ff2(wq[cc*4+kp], hp1[kp], a1);
            }
            float x0, y0, x1, y1;
            up2(a0, x0, y0); up2(a1, x1, y1);
            r0[cc] = x0 + y0; r1[cc] = x1 + y1;
        }
        *(float4*)(ps0)     = make_float4(r0[0], r0[1], r0[2], r0[3]);
        *(float4*)(ps0 + 4) = make_float4(r0[4], r0[5], r0[6], r0[7]);
        *(float4*)(ps1)     = make_float4(r1[0], r1[1], r1[2], r1[3]);
        *(float4*)(ps1 + 4) = make_float4(r1[4], r1[5], r1[6], r1[7]);
        __syncthreads();

        // ---- reduce over 16 k-groups + add gate preactivation ----
        {
            float ssum = gcur;
#pragma unroll
            for (int kgi = 0; kgi < 16; kgi++) ssum += pred[kgi*PCOL];
            gbuf[colr*2 + br] = ssum;
        }
        gcur = gnext;
        __syncthreads();

        // ---- LSTM cell update ----
        if (tid < 128) {
            float iv = gbuf[(      nl)*2 + bu];
            float fv = gbuf[( 64 + nl)*2 + bu];
            float gv = gbuf[(128 + nl)*2 + bu];
            float ov = gbuf[(192 + nl)*2 + bu];
            creg = sigf(fv)*creg + sigf(iv)*tanhf(gv);
            float h = sigf(ov)*tanhf(creg);
            int hoff = (((s+1) & 1)*2 + bu)*128 + ng;
            hbuf[hoff] = h;
            asm volatile("st.shared::cluster.f32 [%0], %1;"
                         :: "r"(hbuf_r + (unsigned)hoff*4), "f"(h) : "memory");
            int t = dir ? (TT-1-s) : s;
            Xout[((size_t)t*BB + bglob_u)*HD1 + dir*HH + ng] = h;
        }
        asm volatile("barrier.cluster.arrive.aligned;" ::: "memory");
        asm volatile("barrier.cluster.wait.aligned;"   ::: "memory");
    }
}

// ---------------- post: BN1+Linear+tanh+BN2+output-proj fused -> g_HL ----------------
__global__ void __launch_bounds__(256) k_post()
{
    __shared__ float as[16][64];
    __shared__ float bs[16][64];
    __shared__ float Hs[64][65];
    __shared__ float wh[2*HD2];
    __shared__ float hbb[2];
    int tid = threadIdx.x;
    int row0 = blockIdx.x*64;
    if (tid < 128) wh[tid] = g_Wh2[tid];
    if (tid < 2)   hbb[tid] = g_hb[tid];

    int lr = tid >> 2, kq = (tid & 3)*4;
    const float* arow = g_X2 + (size_t)(row0 + lr)*HD1;
    const float* wrow = g_Wp + lr*HD1;
    int rowgrp = tid >> 4, colgrp = tid & 15;
    float acc[4][4];
#pragma unroll
    for (int i = 0; i < 4; i++)
#pragma unroll
        for (int j = 0; j < 4; j++) acc[i][j] = 0.f;

    for (int kt = 0; kt < 16; ++kt) {
        int k0 = kt*16;
        float4 av = *(const float4*)(arow + k0 + kq);
        float4 bv = *(const float4*)(wrow + k0 + kq);
        __syncthreads();
        as[kq+0][lr]=av.x; as[kq+1][lr]=av.y; as[kq+2][lr]=av.z; as[kq+3][lr]=av.w;
        bs[kq+0][lr]=bv.x; bs[kq+1][lr]=bv.y; bs[kq+2][lr]=bv.z; bs[kq+3][lr]=bv.w;
        __syncthreads();
#pragma unroll
        for (int kk = 0; kk < 16; ++kk) {
            float4 a4 = *(const float4*)&as[kk][rowgrp*4];
            float4 b4 = *(const float4*)&bs[kk][colgrp*4];
            acc[0][0]+=a4.x*b4.x; acc[0][1]+=a4.x*b4.y; acc[0][2]+=a4.x*b4.z; acc[0][3]+=a4.x*b4.w;
            acc[1][0]+=a4.y*b4.x; acc[1][1]+=a4.y*b4.y; acc[1][2]+=a4.y*b4.z; acc[1][3]+=a4.y*b4.w;
            acc[2][0]+=a4.z*b4.x; acc[2][1]+=a4.z*b4.y; acc[2][2]+=a4.z*b4.z; acc[2][3]+=a4.z*b4.w;
            acc[3][0]+=a4.w*b4.x; acc[3][1]+=a4.w*b4.y; acc[3][2]+=a4.w*b4.z; acc[3][3]+=a4.w*b4.w;
        }
    }
    __syncthreads();
#pragma unroll
    for (int i = 0; i < 4; i++)
#pragma unroll
        for (int j = 0; j < 4; j++) {
            int c = colgrp*4 + j;
            Hs[rowgrp*4 + i][c] = tanhf(acc[i][j] + g_bp[c]);
        }
    __syncthreads();
    if (tid < 128) {
        int r = tid >> 1, k = tid & 1;
        float a = hbb[k];
#pragma unroll
        for (int c = 0; c < HD2; c++) a += Hs[r][c]*wh[k*HD2 + c];
        g_HL[(size_t)(row0 + r)*2 + k] = a;
    }
}

// ---------------- context scan: 64 independent chains ----------------
__global__ void k_ctx(const float* __restrict__ outw, float* __restrict__ out)
{
    int b = threadIdx.x;
    float W00=outw[0],  W01=outw[1],  W02=outw[2],  W03=outw[3];
    float W10=outw[68], W11=outw[69], W12=outw[70], W13=outw[71];
    float c0=0.f, c1=0.f, c2=0.f, c3=0.f;
    for (int t = 0; t < TT; ++t) {
        float h0 = g_HL[((size_t)t*BB + b)*2 + 0];
        float h1 = g_HL[((size_t)t*BB + b)*2 + 1];
        float l0 = h0 + c0*W00 + c1*W01 + c2*W02 + c3*W03;
        float l1 = h1 + c0*W10 + c1*W11 + c2*W12 + c3*W13;
        float m  = fmaxf(l0, l1);
        float lse = m + __logf(__expf(l0 - m) + __expf(l1 - m));
        float o0 = l0 - lse, o1 = l1 - lse;
        out[((size_t)b*TT + t)*2 + 0] = o0;
        out[((size_t)b*TT + t)*2 + 1] = o1;
        c0 = c2; c1 = c3; c2 = o0; c3 = o1;
    }
}

// ---------------- launch ----------------
extern "C" void kernel_launch(void* const* d_in, const int* in_sizes, int n_in,
                              void* d_out, int out_size)
{
    const float* x        = (const float*)d_in[0];
    const float* w_ih_l0  = (const float*)d_in[1];
    const float* w_hh_l0  = (const float*)d_in[2];
    const float* b_ih_l0  = (const float*)d_in[3];
    const float* b_hh_l0  = (const float*)d_in[4];
    const float* w_ih_l0r = (const float*)d_in[5];
    const float* w_hh_l0r = (const float*)d_in[6];
    const float* b_ih_l0r = (const float*)d_in[7];
    const float* b_hh_l0r = (const float*)d_in[8];
    const float* w_ih_l1  = (const float*)d_in[9];
    const float* w_hh_l1  = (const float*)d_in[10];
    const float* b_ih_l1  = (const float*)d_in[11];
    const float* b_hh_l1  = (const float*)d_in[12];
    const float* w_ih_l1r = (const float*)d_in[13];
    const float* w_hh_l1r = (const float*)d_in[14];
    const float* b_ih_l1r = (const float*)d_in[15];
    const float* b_hh_l1r = (const float*)d_in[16];
    const float* bn1_g    = (const float*)d_in[17];
    const float* bn1_b    = (const float*)d_in[18];
    const float* bn1_m    = (const float*)d_in[19];
    const float* bn1_v    = (const float*)d_in[20];
    const float* lin_w    = (const float*)d_in[21];
    const float* lin_b    = (const float*)d_in[22];
    const float* bn2_g    = (const float*)d_in[23];
    const float* bn2_b    = (const float*)d_in[24];
    const float* bn2_m    = (const float*)d_in[25];
    const float* bn2_v    = (const float*)d_in[26];
    const float* out_w    = (const float*)d_in[27];
    const float* out_b    = (const float*)d_in[28];

    k_prep<<<1, 256>>>(bn1_g, bn1_b, bn1_m, bn1_v, lin_w, lin_b,
                       bn2_g, bn2_b, bn2_m, bn2_v, out_w, out_b);

    dim3 gg(NROW/128, G4/128, 2);
    k_gemm<<<gg, 256>>>(x, w_ih_l0, b_ih_l0, b_hh_l0,
                           w_ih_l0r, b_ih_l0r, b_hh_l0r, DIN, 0);
    k_scan<<<dim3(64, 2), 512>>>(w_hh_l0, w_hh_l0r, 0);

    k_gemm<<<gg, 256>>>(x, w_ih_l1, b_ih_l1, b_hh_l1,
                           w_ih_l1r, b_ih_l1r, b_hh_l1r, HD1, 1);
    k_scan<<<dim3(64, 2), 512>>>(w_hh_l1, w_hh_l1r, 1);

    k_post<<<NROW/64, 256>>>();
    k_ctx<<<1, 64>>>(out_w, (float*)d_out);
}